// round 16
// baseline (speedup 1.0000x reference)
#include <cuda_runtime.h>
#include <cuda_bf16.h>

#define N_NODES 100000
#define N_EDGES 1600000
#define D 32
#define SLOT 64    // padded bucket capacity per dst (Poisson(16): P(deg>=64) ~ 1e-18)
#define NB 8       // nodes per warp batch in combine; 100000 % 8 == 0

typedef unsigned long long u64;

// Scratch (device globals: no allocations allowed anywhere)
__device__ int   g_cnt[N_NODES];            // degree / placement cursor
__device__ int   g_slot[N_NODES * SLOT];    // bucketed src indices per dst
__device__ float g_nv[N_NODES * D];         // neighbor mean (gather kernel output)

// packed f32x2 helpers (sm_100+)
#define FMA_F32X2(acc, w, x) \
    asm("fma.rn.f32x2 %0, %1, %2, %0;" : "+l"(acc) : "l"(w), "l"(x))
#define PACK_F32X2_(out, lo, hi) \
    asm("mov.b64 %0, {%1, %2};" : "=l"(out) : "f"(lo), "f"(hi))
#define UNPACK_F32X2_(lo, hi, in) \
    asm("mov.b64 {%0, %1}, %2;" : "=f"(lo), "=f"(hi) : "l"(in))

// ---------------------------------------------------------------------------
// Kernel 0: empty pad — shifts the ncu-profiled slot (abs launch idx 3) onto
// gather_kernel this round.
// ---------------------------------------------------------------------------
__global__ void pad_kernel() {}

// ---------------------------------------------------------------------------
// Kernel 1: zero per-node counters (400 KB), vectorized.
// ---------------------------------------------------------------------------
__global__ void zero_kernel() {
    int tid = blockIdx.x * blockDim.x + threadIdx.x;
    const int n4 = N_NODES / 4;
    int4 z = make_int4(0, 0, 0, 0);
    for (int i = tid; i < n4; i += gridDim.x * blockDim.x)
        reinterpret_cast<int4*>(g_cnt)[i] = z;
    for (int i = n4 * 4 + tid; i < N_NODES; i += gridDim.x * blockDim.x)
        g_cnt[i] = 0;
}

// ---------------------------------------------------------------------------
// Kernel 2: bucket build. 2 edges per thread, int2 index loads (R13: int4
// regressed). ONE int atomic + one scattered store per edge.
// ---------------------------------------------------------------------------
__global__ void bucket_kernel(const int* __restrict__ src,
                              const int* __restrict__ dst,
                              int n_edges) {
    int t = blockIdx.x * blockDim.x + threadIdx.x;
    int e = t * 2;
    if (e + 1 < n_edges) {
        int2 s2 = *reinterpret_cast<const int2*>(&src[e]);
        int2 d2 = *reinterpret_cast<const int2*>(&dst[e]);
        int p0 = atomicAdd(&g_cnt[d2.x], 1);
        int p1 = atomicAdd(&g_cnt[d2.y], 1);
        if (p0 < SLOT) g_slot[d2.x * SLOT + p0] = s2.x;
        if (p1 < SLOT) g_slot[d2.y * SLOT + p1] = s2.y;
    } else if (e < n_edges) {
        int s = src[e], d = dst[e];
        int p = atomicAdd(&g_cnt[d], 1);
        if (p < SLOT) g_slot[d * SLOT + p] = s;
    }
}

// ---------------------------------------------------------------------------
// Kernel 3: gather + mean. NEW: 4 nodes per warp, one 8-lane group per node.
//  - no cross-group reduce (each group owns its node's full row)
//  - idx prefetch: 1 LDG.32 per 8 neighbors + 1 SHFL.IDX each
//  - store: 4 consecutive nodes x 128B = one fully-coalesced 512B warp store
// ---------------------------------------------------------------------------
__global__ void __launch_bounds__(256, 8)
gather_kernel(const float* __restrict__ feat) {
    const float4* __restrict__ feat4 = reinterpret_cast<const float4*>(feat);
    float4* __restrict__ nv4 = reinterpret_cast<float4*>(g_nv);

    int t    = threadIdx.x;        // 256 threads = 8 warps
    int lane = t & 31;
    int wid  = t >> 5;
    int g    = lane >> 3;          // group 0..3 -> node qbase+g
    int gl   = lane & 7;           // lane-in-group: owns cols 4*gl..4*gl+3
    int gsel = lane & 24;          // g*8, shfl source base

    int warps_per_grid = gridDim.x * (blockDim.x >> 5);

    // N_NODES % 4 == 0: every quad is full.
    for (int qbase = (blockIdx.x * 8 + wid) * 4; qbase < N_NODES;
         qbase += warps_per_grid * 4) {
        int4 c4 = *reinterpret_cast<const int4*>(&g_cnt[qbase]);
        int deg = (g == 0) ? c4.x : (g == 1) ? c4.y : (g == 2) ? c4.z : c4.w;
        int dc  = min(deg, SLOT);
        int rmax = max(max(min(c4.x, SLOT), min(c4.y, SLOT)),
                       max(min(c4.z, SLOT), min(c4.w, SLOT)));

        const int* row = &g_slot[(size_t)(qbase + g) * SLOT];

        float4 acc = make_float4(0.f, 0.f, 0.f, 0.f);
        for (int rb = 0; rb < rmax; rb += 8) {
            int idx8 = row[rb + gl];          // rb+gl <= 63: always safe
#pragma unroll
            for (int j = 0; j < 8; ++j) {
                int s = __shfl_sync(0xffffffffu, idx8, gsel | j);
                if (rb + j < dc) {
                    float4 v = feat4[(size_t)s * 8 + gl];
                    acc.x += v.x; acc.y += v.y; acc.z += v.z; acc.w += v.w;
                }
            }
        }

        float inv = 1.0f / fmaxf((float)deg, 1.0f);
        float4 nvv;
        nvv.x = acc.x * inv; nvv.y = acc.y * inv;
        nvv.z = acc.z * inv; nvv.w = acc.w * inv;
        nv4[(size_t)(qbase + g) * 8 + gl] = nvv;   // 512B coalesced per warp
    }
}

// ---------------------------------------------------------------------------
// Kernel 4: combine (streaming), 8 nodes per warp, fully unrolled staging.
// (R15 profile: 27.7us, at the LDS-broadcast floor of this dataflow.)
// ---------------------------------------------------------------------------
__global__ void __launch_bounds__(256, 6)
combine_kernel(const float* __restrict__ feat,
               const float* __restrict__ W_self,
               const float* __restrict__ W_neigh,
               const float* __restrict__ b_neigh,
               float* __restrict__ out) {
    // wq[j*32+lane] = ( (Ws[l][2j],Wn[l][2j]) , (Ws[l][2j+1],Wn[l][2j+1]) )
    __shared__ ulonglong2 wq[(D / 2) * D];
    __shared__ u64 fnv[8][NB][D];      // fnv[k] = (f[k], nv[k]) packed
    __shared__ float bs[D];

    int t    = threadIdx.x;        // 256 threads = 8 warps
    int lane = t & 31;
    int wid  = t >> 5;

    for (int i = t; i < (D / 2) * D; i += blockDim.x) {
        int j = i >> 5, l = i & 31;
        u64 w0, w1;
        PACK_F32X2_(w0, W_self[l * D + 2 * j + 0], W_neigh[l * D + 2 * j + 0]);
        PACK_F32X2_(w1, W_self[l * D + 2 * j + 1], W_neigh[l * D + 2 * j + 1]);
        ulonglong2 q; q.x = w0; q.y = w1;
        wq[i] = q;
    }
    if (t < D) bs[t] = b_neigh[t];
    __syncthreads();

    int warps_per_grid = gridDim.x * (blockDim.x >> 5);

    for (int base = (blockIdx.x * 8 + wid) * NB; base < N_NODES;
         base += warps_per_grid * NB) {

        // ---- stage (f, nv): 16 independent LDGs, fully unrolled
        u64 pk[NB];
#pragma unroll
        for (int b = 0; b < NB; ++b) {
            float f   = feat[(size_t)(base + b) * D + lane];
            float nvv = g_nv[(size_t)(base + b) * D + lane];
            PACK_F32X2_(pk[b], f, nvv);
        }
#pragma unroll
        for (int b = 0; b < NB; ++b) fnv[wid][b][lane] = pk[b];
        __syncwarp();

        // ---- combine: each weight quad loaded once for all NB nodes
        u64 a[NB];
#pragma unroll
        for (int b = 0; b < NB; ++b) a[b] = 0ull;

#pragma unroll
        for (int j = 0; j < D / 2; ++j) {       // j covers k = 2j, 2j+1
            ulonglong2 w = wq[j * D + lane];    // LDS.128, once per 8 nodes
#pragma unroll
            for (int b = 0; b < NB; ++b) {
                ulonglong2 v =
                    reinterpret_cast<const ulonglong2*>(fnv[wid][b])[j];
                FMA_F32X2(a[b], w.x, v.x);
                FMA_F32X2(a[b], w.y, v.y);
            }
        }
#pragma unroll
        for (int b = 0; b < NB; ++b) {
            float lo, hi;
            UNPACK_F32X2_(lo, hi, a[b]);
            out[(size_t)(base + b) * D + lane] = bs[lane] + lo + hi;
        }
        __syncwarp();   // reads done before next iteration's fnv stores
    }
}

// ---------------------------------------------------------------------------
// Launch
// Inputs: feat[N,32] f32, W_self[32,32], W_neigh[32,32], b_neigh[32],
// src[E] i32, dst[E] i32. Output: [N,32] f32.
// Order: pad(0) zero(1) bucket(2) gather(3 -> profiled) combine(4).
// ---------------------------------------------------------------------------
extern "C" void kernel_launch(void* const* d_in, const int* in_sizes, int n_in,
                              void* d_out, int out_size) {
    const float* feat    = (const float*)d_in[0];
    const float* W_self  = (const float*)d_in[1];
    const float* W_neigh = (const float*)d_in[2];
    const float* b_neigh = (const float*)d_in[3];
    const int*   src     = (const int*)d_in[4];
    const int*   dst     = (const int*)d_in[5];
    float* out = (float*)d_out;

    const int n_edges = in_sizes[4];

    pad_kernel<<<1, 32>>>();                                             // 0
    zero_kernel<<<296, 256>>>();                                         // 1
    int bthreads = (n_edges + 1) / 2;
    bucket_kernel<<<(bthreads + 255) / 256, 256>>>(src, dst, n_edges);   // 2
    gather_kernel<<<1184, 256>>>(feat);                                  // 3 -> profiled
    combine_kernel<<<888, 256>>>(feat, W_self, W_neigh, b_neigh, out);   // 4
}

// round 17
// speedup vs baseline: 1.1216x; 1.1216x over previous
#include <cuda_runtime.h>
#include <cuda_bf16.h>

#define N_NODES 100000
#define N_EDGES 1600000
#define D 32
#define SLOT 64    // padded bucket capacity per dst (Poisson(16): P(deg>=64) ~ 1e-18)
#define NB 8       // nodes per warp batch; N_NODES % NB == 0 -> batches always full

typedef unsigned long long u64;

// Scratch (device globals: zero-initialized at module load; no allocs allowed)
__device__ int g_cnt[N_NODES];            // degree / placement cursor
__device__ int g_slot[N_NODES * SLOT];    // bucketed src indices per dst

// packed f32x2 helpers (sm_100+)
#define FMA_F32X2(acc, w, x) \
    asm("fma.rn.f32x2 %0, %1, %2, %0;" : "+l"(acc) : "l"(w), "l"(x))
#define PACK_F32X2_(out, lo, hi) \
    asm("mov.b64 %0, {%1, %2};" : "=l"(out) : "f"(lo), "f"(hi))
#define UNPACK_F32X2_(lo, hi, in) \
    asm("mov.b64 {%0, %1}, %2;" : "=f"(lo), "=f"(hi) : "l"(in))

// ---------------------------------------------------------------------------
// Kernel 1: bucket build. 2 edges per thread, int2 index loads (R13: int4
// regressed). ONE int atomic + one scattered store per edge. Counters were
// left zeroed by the previous agg pass (or static zero-init on first run).
// ---------------------------------------------------------------------------
__global__ void bucket_kernel(const int* __restrict__ src,
                              const int* __restrict__ dst,
                              int n_edges) {
    int t = blockIdx.x * blockDim.x + threadIdx.x;
    int e = t * 2;
    if (e + 1 < n_edges) {
        int2 s2 = *reinterpret_cast<const int2*>(&src[e]);
        int2 d2 = *reinterpret_cast<const int2*>(&dst[e]);
        int p0 = atomicAdd(&g_cnt[d2.x], 1);
        int p1 = atomicAdd(&g_cnt[d2.y], 1);
        if (p0 < SLOT) g_slot[d2.x * SLOT + p0] = s2.x;
        if (p1 < SLOT) g_slot[d2.y * SLOT + p1] = s2.y;
    } else if (e < n_edges) {
        int s = src[e], d = dst[e];
        int p = atomicAdd(&g_cnt[d], 1);
        if (p < SLOT) g_slot[d * SLOT + p] = s;
    }
}

// ---------------------------------------------------------------------------
// Kernel 2: fused aggregate + combine, 8 nodes per warp (EXACT R11 dataflow,
// proven 50.4us @ (256,6)). New here:
//  - batches are compile-time FULL (N_NODES % 8 == 0) -> unrolled loops
//  - resets g_cnt[base..base+7] after consumption (replaces zero_kernel);
//    two int4 stores from lanes 0-1 = 1 wavefront per 8 nodes.
// ---------------------------------------------------------------------------
__global__ void __launch_bounds__(256, 6)
agg_combine_kernel(const float* __restrict__ feat,
                   const float* __restrict__ W_self,
                   const float* __restrict__ W_neigh,
                   const float* __restrict__ b_neigh,
                   float* __restrict__ out) {
    // wq[j*32+lane] = ( (Ws[l][2j],Wn[l][2j]) , (Ws[l][2j+1],Wn[l][2j+1]) )
    __shared__ ulonglong2 wq[(D / 2) * D];
    __shared__ u64 fnv[8][NB][D];      // per-warp, per-batch-node: (f[k], nv[k])
    __shared__ float bs[D];

    const float4* __restrict__ feat4 = reinterpret_cast<const float4*>(feat);

    int t    = threadIdx.x;        // 256 threads = 8 warps
    int lane = t & 31;
    int wid  = t >> 5;
    int g    = lane >> 3;          // gather group 0..3
    int gl   = lane & 7;           // lane-in-group: owns cols 4*gl..4*gl+3

    for (int i = t; i < (D / 2) * D; i += blockDim.x) {
        int j = i >> 5, l = i & 31;       // j = k-pair index, l = out column
        u64 w0, w1;
        PACK_F32X2_(w0, W_self[l * D + 2 * j + 0], W_neigh[l * D + 2 * j + 0]);
        PACK_F32X2_(w1, W_self[l * D + 2 * j + 1], W_neigh[l * D + 2 * j + 1]);
        ulonglong2 q; q.x = w0; q.y = w1;
        wq[i] = q;
    }
    if (t < D) bs[t] = b_neigh[t];
    __syncthreads();

    int warps_per_grid = gridDim.x * (blockDim.x >> 5);

    // base is a multiple of NB; N_NODES % NB == 0 -> batch always full.
    for (int base = (blockIdx.x * 8 + wid) * NB; base < N_NODES;
         base += warps_per_grid * NB) {

        // ---- gather phase: NB nodes sequentially (independent chains)
        for (int b = 0; b < NB; ++b) {
            int node = base + b;
            int deg = g_cnt[node];
            int dc = min(deg, SLOT);
            const int* row = &g_slot[(size_t)node * SLOT];
            int rounds = (dc + 3) >> 2;

            float4 acc = make_float4(0.f, 0.f, 0.f, 0.f);
#pragma unroll 4
            for (int r = 0; r < rounds; ++r) {
                int p = 4 * r + g;          // p <= 63 always: safe to read
                int s = row[p];
                if (p < dc) {
                    float4 v = feat4[(size_t)s * 8 + gl];
                    acc.x += v.x; acc.y += v.y; acc.z += v.z; acc.w += v.w;
                }
            }
#pragma unroll
            for (int off = 8; off < 32; off <<= 1) {
                acc.x += __shfl_xor_sync(0xffffffffu, acc.x, off);
                acc.y += __shfl_xor_sync(0xffffffffu, acc.y, off);
                acc.z += __shfl_xor_sync(0xffffffffu, acc.z, off);
                acc.w += __shfl_xor_sync(0xffffffffu, acc.w, off);
            }

            float f = feat[(size_t)node * D + lane];
            ((float*)&fnv[wid][b][lane])[0] = f;          // low half = f[k]
            if (lane < 8) {
                float inv = 1.0f / fmaxf((float)deg, 1.0f);
                ((float*)&fnv[wid][b][4 * gl + 0])[1] = acc.x * inv;
                ((float*)&fnv[wid][b][4 * gl + 1])[1] = acc.y * inv;
                ((float*)&fnv[wid][b][4 * gl + 2])[1] = acc.z * inv;
                ((float*)&fnv[wid][b][4 * gl + 3])[1] = acc.w * inv;
            }
        }
        __syncwarp();

        // ---- reset counters for this batch (replaces zero_kernel).
        // g_cnt[base..base+7]: two int4 zero-stores, base is 8-aligned.
        if (lane < 2) {
            reinterpret_cast<int4*>(&g_cnt[base])[lane] = make_int4(0, 0, 0, 0);
        }

        // ---- combine phase: each weight quad loaded ONCE for all NB nodes
        u64 a[NB];
#pragma unroll
        for (int b = 0; b < NB; ++b) a[b] = 0ull;

#pragma unroll
        for (int j = 0; j < D / 2; ++j) {       // j covers k = 2j, 2j+1
            ulonglong2 w = wq[j * D + lane];    // LDS.128, once per 8 nodes
#pragma unroll
            for (int b = 0; b < NB; ++b) {
                ulonglong2 v =
                    reinterpret_cast<const ulonglong2*>(fnv[wid][b])[j];
                FMA_F32X2(a[b], w.x, v.x);
                FMA_F32X2(a[b], w.y, v.y);
            }
        }
#pragma unroll
        for (int b = 0; b < NB; ++b) {
            float lo, hi;
            UNPACK_F32X2_(lo, hi, a[b]);
            out[(size_t)(base + b) * D + lane] = bs[lane] + lo + hi;
        }
        __syncwarp();   // reads done before next iteration's fnv stores
    }
}

// ---------------------------------------------------------------------------
// Launch
// Inputs: feat[N,32] f32, W_self[32,32], W_neigh[32,32], b_neigh[32],
// src[E] i32, dst[E] i32. Output: [N,32] f32.
// Two launches: bucket(0), agg(1) — profiled slot (abs idx 3 -> 3 mod 2 = 1)
// lands on agg.
// ---------------------------------------------------------------------------
extern "C" void kernel_launch(void* const* d_in, const int* in_sizes, int n_in,
                              void* d_out, int out_size) {
    const float* feat    = (const float*)d_in[0];
    const float* W_self  = (const float*)d_in[1];
    const float* W_neigh = (const float*)d_in[2];
    const float* b_neigh = (const float*)d_in[3];
    const int*   src     = (const int*)d_in[4];
    const int*   dst     = (const int*)d_in[5];
    float* out = (float*)d_out;

    const int n_edges = in_sizes[4];

    int bthreads = (n_edges + 1) / 2;
    bucket_kernel<<<(bthreads + 255) / 256, 256>>>(src, dst, n_edges);      // 0
    agg_combine_kernel<<<888, 256>>>(feat, W_self, W_neigh, b_neigh, out);  // 1 -> profiled
}